// round 12
// baseline (speedup 1.0000x reference)
#include <cuda_runtime.h>
#include <cuda_bf16.h>
#include <math.h>
#include <stdint.h>

#define EMB    768
#define HEADS  12
#define DEPTH  64
#define BATCH  2
#define SEQ    4096
#define MROWS  (BATCH * SEQ)      // 8192
#define BH     (BATCH * HEADS)    // 24

typedef unsigned int  u32;
typedef unsigned short u16;

// ---------------------------------------------------------------------------
// Scratch (allocation-free device globals), all bf16 hi/lo split pairs.
// ---------------------------------------------------------------------------
__device__ u16 g_xh[MROWS * EMB],  g_xl[MROWS * EMB];
__device__ u16 g_Wqh[EMB * EMB],   g_Wql[EMB * EMB];
__device__ u16 g_Wkh[EMB * EMB],   g_Wkl[EMB * EMB];
__device__ u16 g_Wvh[EMB * EMB],   g_Wvl[EMB * EMB];
__device__ u16 g_Woh[EMB * EMB],   g_Wol[EMB * EMB];
__device__ u16 g_Qh[MROWS * EMB],  g_Ql[MROWS * EMB];   // Q pre-scaled by 0.125
__device__ u16 g_Kh[MROWS * EMB],  g_Kl[MROWS * EMB];
__device__ u16 g_Vh[MROWS * EMB],  g_Vl[MROWS * EMB];
__device__ u16 g_Vth[BH * DEPTH * SEQ], g_Vtl[BH * DEPTH * SEQ]; // V^T [bh][d][s]
__device__ u16 g_Oh[MROWS * EMB],  g_Ol[MROWS * EMB];

// ---------------------------------------------------------------------------
// Helpers
// ---------------------------------------------------------------------------
__device__ __forceinline__ void split1(float v, u16& h, u16& l) {
    __nv_bfloat16 hb = __float2bfloat16(v);
    __nv_bfloat16 lb = __float2bfloat16(v - __bfloat162float(hb));
    h = __bfloat16_as_ushort(hb);
    l = __bfloat16_as_ushort(lb);
}
__device__ __forceinline__ void split2(float v0, float v1, u32& h, u32& l) {
    u16 h0, l0, h1, l1;
    split1(v0, h0, l0); split1(v1, h1, l1);
    h = (u32)h0 | ((u32)h1 << 16);
    l = (u32)l0 | ((u32)l1 << 16);
}

// m16n8k16 row.col bf16 mma, fp32 accumulate (base-ISA, sm_80+)
__device__ __forceinline__ void mma16816(float* c, const u32* a, const u32* b) {
    asm volatile(
        "mma.sync.aligned.m16n8k16.row.col.f32.bf16.bf16.f32 "
        "{%0,%1,%2,%3}, {%4,%5,%6,%7}, {%8,%9}, {%0,%1,%2,%3};"
        : "+f"(c[0]), "+f"(c[1]), "+f"(c[2]), "+f"(c[3])
        : "r"(a[0]), "r"(a[1]), "r"(a[2]), "r"(a[3]), "r"(b[0]), "r"(b[1]));
}

__device__ __forceinline__ u32 smaddr(const void* p) {
    return (u32)__cvta_generic_to_shared(p);
}
__device__ __forceinline__ void ldsm4(u32& r0, u32& r1, u32& r2, u32& r3, u32 a) {
    asm volatile("ldmatrix.sync.aligned.m8n8.x4.shared.b16 {%0,%1,%2,%3}, [%4];"
                 : "=r"(r0), "=r"(r1), "=r"(r2), "=r"(r3) : "r"(a));
}

// ---------------------------------------------------------------------------
// 1) fp32 -> bf16 hi/lo elementwise converts
// ---------------------------------------------------------------------------
__global__ __launch_bounds__(256) void convert_kernel(const float* __restrict__ src,
                                                      u16* __restrict__ dh,
                                                      u16* __restrict__ dl, int n)
{
    int i = (blockIdx.x * 256 + threadIdx.x) * 4;
    if (i >= n) return;
    float4 v = *(const float4*)(src + i);
    u16 h0,l0,h1,l1,h2,l2,h3,l3;
    split1(v.x,h0,l0); split1(v.y,h1,l1); split1(v.z,h2,l2); split1(v.w,h3,l3);
    *(uint2*)(dh + i) = make_uint2((u32)h0 | ((u32)h1<<16), (u32)h2 | ((u32)h3<<16));
    *(uint2*)(dl + i) = make_uint2((u32)l0 | ((u32)l1<<16), (u32)l2 | ((u32)l3<<16));
}

__global__ __launch_bounds__(256) void convert_w_kernel(const float* __restrict__ Wq,
                                                        const float* __restrict__ Wk,
                                                        const float* __restrict__ Wv,
                                                        const float* __restrict__ Wo)
{
    const float* src; u16 *dh, *dl;
    switch (blockIdx.y) {
        case 0:  src = Wq; dh = g_Wqh; dl = g_Wql; break;
        case 1:  src = Wk; dh = g_Wkh; dl = g_Wkl; break;
        case 2:  src = Wv; dh = g_Wvh; dl = g_Wvl; break;
        default: src = Wo; dh = g_Woh; dl = g_Wol; break;
    }
    int i = (blockIdx.x * 256 + threadIdx.x) * 4;
    if (i >= EMB * EMB) return;
    float4 v = *(const float4*)(src + i);
    u16 h0,l0,h1,l1,h2,l2,h3,l3;
    split1(v.x,h0,l0); split1(v.y,h1,l1); split1(v.z,h2,l2); split1(v.w,h3,l3);
    *(uint2*)(dh + i) = make_uint2((u32)h0 | ((u32)h1<<16), (u32)h2 | ((u32)h3<<16));
    *(uint2*)(dl + i) = make_uint2((u32)l0 | ((u32)l1<<16), (u32)l2 | ((u32)l3<<16));
}

// ---------------------------------------------------------------------------
// 2) 128x128 GEMM tile via mma.sync, split-3 bf16 (unchanged; passing)
// ---------------------------------------------------------------------------
#define GS_PAD 72
#define G_TILE (128 * GS_PAD)
#define GEMM_SMEM_BYTES (4 * G_TILE * 2)   // 73728 B

__device__ __forceinline__ void gemm128(const u16* __restrict__ Ah, const u16* __restrict__ Al,
                                        const u16* __restrict__ Wh, const u16* __restrict__ Wl,
                                        int row0, int col0,
                                        int mode, float alpha,
                                        u16* __restrict__ outH, u16* __restrict__ outL,
                                        float* __restrict__ outF, const float* __restrict__ bias)
{
    extern __shared__ char smraw[];
    u16* sAh = (u16*)smraw;
    u16* sAl = sAh + G_TILE;
    u16* sWh = sAl + G_TILE;
    u16* sWl = sWh + G_TILE;

    const int tid  = threadIdx.x;
    const int warp = tid >> 5, lane = tid & 31;
    const int g = lane >> 2, t = lane & 3;
    const int r0  = (warp >> 1) * 32;
    const int c0w = (warp & 1) * 64;

    float acc[2][8][4];
#pragma unroll
    for (int i = 0; i < 2; i++)
#pragma unroll
        for (int n = 0; n < 8; n++)
#pragma unroll
            for (int q = 0; q < 4; q++) acc[i][n][q] = 0.f;

    for (int kc = 0; kc < EMB; kc += 64) {
#pragma unroll
        for (int u = tid; u < 1024; u += 256) {
            int row = u >> 3, q = u & 7;
            size_t ia = (size_t)(row0 + row) * EMB + kc + q * 8;
            size_t iw = (size_t)(col0 + row) * EMB + kc + q * 8;
            *(uint4*)(sAh + row * GS_PAD + q * 8) = *(const uint4*)(Ah + ia);
            *(uint4*)(sAl + row * GS_PAD + q * 8) = *(const uint4*)(Al + ia);
            *(uint4*)(sWh + row * GS_PAD + q * 8) = *(const uint4*)(Wh + iw);
            *(uint4*)(sWl + row * GS_PAD + q * 8) = *(const uint4*)(Wl + iw);
        }
        __syncthreads();

#pragma unroll
        for (int kb = 0; kb < 4; kb++) {
            const int kk = kb * 16 + 2 * t;
            u32 ah[2][4], al[2][4];
#pragma unroll
            for (int i = 0; i < 2; i++) {
                int rb = r0 + 16 * i;
                ah[i][0] = *(const u32*)(sAh + (rb + g    ) * GS_PAD + kk);
                ah[i][1] = *(const u32*)(sAh + (rb + g + 8) * GS_PAD + kk);
                ah[i][2] = *(const u32*)(sAh + (rb + g    ) * GS_PAD + kk + 8);
                ah[i][3] = *(const u32*)(sAh + (rb + g + 8) * GS_PAD + kk + 8);
                al[i][0] = *(const u32*)(sAl + (rb + g    ) * GS_PAD + kk);
                al[i][1] = *(const u32*)(sAl + (rb + g + 8) * GS_PAD + kk);
                al[i][2] = *(const u32*)(sAl + (rb + g    ) * GS_PAD + kk + 8);
                al[i][3] = *(const u32*)(sAl + (rb + g + 8) * GS_PAD + kk + 8);
            }
#pragma unroll
            for (int n = 0; n < 8; n++) {
                int wr = (c0w + 8 * n + g) * GS_PAD;
                u32 bh[2] = { *(const u32*)(sWh + wr + kk), *(const u32*)(sWh + wr + kk + 8) };
                u32 bl[2] = { *(const u32*)(sWl + wr + kk), *(const u32*)(sWl + wr + kk + 8) };
#pragma unroll
                for (int i = 0; i < 2; i++) {
                    mma16816(acc[i][n], ah[i], bh);
                    mma16816(acc[i][n], ah[i], bl);
                    mma16816(acc[i][n], al[i], bh);
                }
            }
        }
        __syncthreads();
    }

    float* Cs = (float*)smraw;             // [128][132]
#pragma unroll
    for (int i = 0; i < 2; i++)
#pragma unroll
        for (int n = 0; n < 8; n++) {
            int r = r0 + 16 * i + g, c = c0w + 8 * n + 2 * t;
            *(float2*)(Cs + (r    ) * 132 + c) = make_float2(acc[i][n][0], acc[i][n][1]);
            *(float2*)(Cs + (r + 8) * 132 + c) = make_float2(acc[i][n][2], acc[i][n][3]);
        }
    __syncthreads();

#pragma unroll
    for (int u = tid; u < 128 * 32; u += 256) {
        int r = u >> 5, c4 = (u & 31) * 4;
        float4 v = *(const float4*)(Cs + r * 132 + c4);
        size_t o = (size_t)(row0 + r) * EMB + col0 + c4;
        if (mode == 0) {
            v.x *= alpha; v.y *= alpha; v.z *= alpha; v.w *= alpha;
            u16 h0,l0,h1,l1,h2,l2,h3,l3;
            split1(v.x,h0,l0); split1(v.y,h1,l1); split1(v.z,h2,l2); split1(v.w,h3,l3);
            *(uint2*)(outH + o) = make_uint2((u32)h0|((u32)h1<<16), (u32)h2|((u32)h3<<16));
            *(uint2*)(outL + o) = make_uint2((u32)l0|((u32)l1<<16), (u32)l2|((u32)l3<<16));
        } else {
            float4 bv = *(const float4*)(bias + col0 + c4);
            v.x += bv.x; v.y += bv.y; v.z += bv.z; v.w += bv.w;
            *(float4*)(outF + o) = v;
        }
    }
}

__global__ __launch_bounds__(256) void qkv_kernel()
{
    int nt = blockIdx.x, sel = nt / 6;
    int col0 = (nt % 6) * 128, row0 = blockIdx.y * 128;
    const u16 *Wh, *Wl; u16 *oh, *ol; float alpha;
    if (sel == 0)      { Wh = g_Wqh; Wl = g_Wql; oh = g_Qh; ol = g_Ql; alpha = 0.125f; }
    else if (sel == 1) { Wh = g_Wkh; Wl = g_Wkl; oh = g_Kh; ol = g_Kl; alpha = 1.f; }
    else               { Wh = g_Wvh; Wl = g_Wvl; oh = g_Vh; ol = g_Vl; alpha = 1.f; }
    gemm128(g_xh, g_xl, Wh, Wl, row0, col0, 0, alpha, oh, ol, nullptr, nullptr);
}

__global__ __launch_bounds__(256) void proj_kernel(float* __restrict__ out,
                                                   const float* __restrict__ bias)
{
    gemm128(g_Oh, g_Ol, g_Woh, g_Wol, blockIdx.y * 128, blockIdx.x * 128,
            1, 1.f, nullptr, nullptr, out, bias);
}

// ---------------------------------------------------------------------------
// 3) V transpose: g_Vh/l [b][s][h*64+d] -> g_Vth/l [bh][d][s]
// ---------------------------------------------------------------------------
__global__ __launch_bounds__(256) void vtrans_kernel()
{
    __shared__ u16 Vh_s[64][GS_PAD], Vl_s[64][GS_PAD];
    int bh = blockIdx.y, b = bh / HEADS, h = bh % HEADS;
    int k0 = blockIdx.x * 64;
    int tid = threadIdx.x;
#pragma unroll
    for (int u = tid; u < 512; u += 256) {
        int row = u >> 3, q = u & 7;
        size_t i = (size_t)(b * SEQ + k0 + row) * EMB + h * 64 + q * 8;
        *(uint4*)(&Vh_s[row][q * 8]) = *(const uint4*)(g_Vh + i);
        *(uint4*)(&Vl_s[row][q * 8]) = *(const uint4*)(g_Vl + i);
    }
    __syncthreads();
#pragma unroll
    for (int u = tid; u < 4096; u += 256) {
        int d = u >> 6, key = u & 63;
        size_t o = ((size_t)bh * DEPTH + d) * SEQ + k0 + key;
        g_Vth[o] = Vh_s[key][d];
        g_Vtl[o] = Vl_s[key][d];
    }
}

// ---------------------------------------------------------------------------
// 4) Flash attention v4 = R7 structure (64q tiles, 4 warps, plain LDG->STS
//    tile loads with L1 reuse) + ldmatrix fragment loads (only change).
// ---------------------------------------------------------------------------
#define AP 72                              // u16 per smem row (144 B, 16B-aligned)
#define ARR_U16 (64 * AP)                  // one 64-row array

__global__ __launch_bounds__(128) void attn_kernel()
{
    __shared__ __align__(16) u16 smem[4 * ARR_U16];   // 36864 B (R7 size)
    u16* sKh = smem;
    u16* sKl = smem + ARR_U16;
    u16* sVh = smem + 2 * ARR_U16;
    u16* sVl = smem + 3 * ARR_U16;
    const u32 smb = smaddr(smem);

    const int b = blockIdx.z, h = blockIdx.y, qt = blockIdx.x;
    const int tid = threadIdx.x, warp = tid >> 5, lane = tid & 31;
    const int t = lane & 3;
    const int qr = warp * 16;              // warp's query-row base (0..48)

    // ---- stage Q tile (64 rows x 64) into sKh/sKl, extract fragments ----
#pragma unroll
    for (int u = tid; u < 512; u += 128) {
        int row = u >> 3, q = u & 7;
        size_t i = (size_t)(b * SEQ + qt * 64 + row) * EMB + h * 64 + q * 8;
        *(uint4*)(sKh + row * AP + q * 8) = *(const uint4*)(g_Qh + i);
        *(uint4*)(sKl + row * AP + q * 8) = *(const uint4*)(g_Ql + i);
    }
    __syncthreads();

    u32 qh[4][4], ql[4][4];
    {
        u32 abase_h = smb + (u32)((qr + (lane & 15)) * AP) * 2 + (lane >> 4) * 16;
        u32 abase_l = abase_h + (u32)ARR_U16 * 2;
#pragma unroll
        for (int k = 0; k < 4; k++) {
            ldsm4(qh[k][0], qh[k][1], qh[k][2], qh[k][3], abase_h + k * 32);
            ldsm4(ql[k][0], ql[k][1], ql[k][2], ql[k][3], abase_l + k * 32);
        }
    }
    __syncthreads();                       // Q fragments extracted; smem reusable

    float o[8][4];
#pragma unroll
    for (int d = 0; d < 8; d++)
#pragma unroll
        for (int q = 0; q < 4; q++) o[d][q] = 0.f;
    float m0 = -1e30f, m1 = -1e30f, l0 = 0.f, l1 = 0.f;

    // B-fragment per-lane addressing: row (lane&7), 16B-group (lane>>3)
    const u32 brow = (u32)((lane & 7) * AP) * 2 + (lane >> 3) * 16;
    const u32 aKh = smb;
    const u32 aKl = smb + (u32)ARR_U16 * 2;
    const u32 aVh = smb + (u32)(2 * ARR_U16) * 2;
    const u32 aVl = smb + (u32)(3 * ARR_U16) * 2;

    for (int kt = 0; kt < SEQ / 64; kt++) {
        // ---- stage K and V^T tiles (plain LDG -> STS, L1-cached reuse) ----
#pragma unroll
        for (int u = tid; u < 512; u += 128) {
            int row = u >> 3, q = u & 7;
            size_t ik = (size_t)(b * SEQ + kt * 64 + row) * EMB + h * 64 + q * 8;
            size_t iv = ((size_t)(b * HEADS + h) * DEPTH + row) * SEQ + kt * 64 + q * 8;
            *(uint4*)(sKh + row * AP + q * 8) = *(const uint4*)(g_Kh + ik);
            *(uint4*)(sKl + row * AP + q * 8) = *(const uint4*)(g_Kl + ik);
            *(uint4*)(sVh + row * AP + q * 8) = *(const uint4*)(g_Vth + iv);
            *(uint4*)(sVl + row * AP + q * 8) = *(const uint4*)(g_Vtl + iv);
        }
        __syncthreads();

        // ---- S = (0.125 Q) K^T, split-3, ldmatrix B-fragments ----
        float S[8][4];
#pragma unroll
        for (int n = 0; n < 8; n++) {
            S[n][0] = S[n][1] = S[n][2] = S[n][3] = 0.f;
            u32 roff = (u32)(8 * n * AP) * 2 + brow;
            u32 kh[8], kl[8];
            ldsm4(kh[0], kh[1], kh[2], kh[3], aKh + roff);
            ldsm4(kh[4], kh[5], kh[6], kh[7], aKh + roff + 64);
            ldsm4(kl[0], kl[1], kl[2], kl[3], aKl + roff);
            ldsm4(kl[4], kl[5], kl[6], kl[7], aKl + roff + 64);
#pragma unroll
            for (int k = 0; k < 4; k++) {
                mma16816(S[n], qh[k], kh + 2 * k);
                mma16816(S[n], qh[k], kl + 2 * k);
                mma16816(S[n], ql[k], kh + 2 * k);
            }
        }

        // ---- online softmax on fragments (rows qr+g, qr+g+8) ----
        float mx0 = -1e30f, mx1 = -1e30f;
#pragma unroll
        for (int n = 0; n < 8; n++) {
            mx0 = fmaxf(mx0, fmaxf(S[n][0], S[n][1]));
            mx1 = fmaxf(mx1, fmaxf(S[n][2], S[n][3]));
        }
        mx0 = fmaxf(mx0, __shfl_xor_sync(0xffffffffu, mx0, 1));
        mx0 = fmaxf(mx0, __shfl_xor_sync(0xffffffffu, mx0, 2));
        mx1 = fmaxf(mx1, __shfl_xor_sync(0xffffffffu, mx1, 1));
        mx1 = fmaxf(mx1, __shfl_xor_sync(0xffffffffu, mx1, 2));
        float mn0 = fmaxf(m0, mx0), mn1 = fmaxf(m1, mx1);
        float c0 = __expf(m0 - mn0), c1 = __expf(m1 - mn1);
        float s0 = 0.f, s1 = 0.f;
#pragma unroll
        for (int n = 0; n < 8; n++) {
            S[n][0] = __expf(S[n][0] - mn0); s0 += S[n][0];
            S[n][1] = __expf(S[n][1] - mn0); s0 += S[n][1];
            S[n][2] = __expf(S[n][2] - mn1); s1 += S[n][2];
            S[n][3] = __expf(S[n][3] - mn1); s1 += S[n][3];
        }
        s0 += __shfl_xor_sync(0xffffffffu, s0, 1);
        s0 += __shfl_xor_sync(0xffffffffu, s0, 2);
        s1 += __shfl_xor_sync(0xffffffffu, s1, 1);
        s1 += __shfl_xor_sync(0xffffffffu, s1, 2);
        l0 = l0 * c0 + s0;  l1 = l1 * c1 + s1;
        m0 = mn0;           m1 = mn1;
#pragma unroll
        for (int d = 0; d < 8; d++) {
            o[d][0] *= c0; o[d][1] *= c0; o[d][2] *= c1; o[d][3] *= c1;
        }

        // ---- P (C-fragment) -> A fragments, split hi/lo ----
        u32 ph[4][4], pl[4][4];
#pragma unroll
        for (int j = 0; j < 4; j++) {
            split2(S[2*j  ][0], S[2*j  ][1], ph[j][0], pl[j][0]);
            split2(S[2*j  ][2], S[2*j  ][3], ph[j][1], pl[j][1]);
            split2(S[2*j+1][0], S[2*j+1][1], ph[j][2], pl[j][2]);
            split2(S[2*j+1][2], S[2*j+1][3], ph[j][3], pl[j][3]);
        }

        // ---- O += P V, split-3, ldmatrix B-fragments from V^T ----
#pragma unroll
        for (int d = 0; d < 8; d++) {
            u32 roff = (u32)(8 * d * AP) * 2 + brow;
            u32 vh[8], vl[8];
            ldsm4(vh[0], vh[1], vh[2], vh[3], aVh + roff);
            ldsm4(vh[4], vh[5], vh[6], vh[7], aVh + roff + 64);
            ldsm4(vl[0], vl[1], vl[2], vl[3], aVl + roff);
            ldsm4(vl[4], vl[5], vl[6], vl[7], aVl + roff + 64);
#pragma unroll
            for (int j = 0; j < 4; j++) {
                mma16816(o[d], ph[j], vh + 2 * j);
                mma16816(o[d], ph[j], vl + 2 * j);
                mma16816(o[d], pl[j], vh + 2 * j);
            }
        }
        __syncthreads();                   // done reading this tile
    }

    // ---- epilogue: normalize, stage via smem, write split O ----
    const int g = lane >> 2;
    float inv0 = 1.f / l0, inv1 = 1.f / l1;
    float* Os = (float*)smem;              // [64][68] fp32 = 17408 B
#pragma unroll
    for (int d = 0; d < 8; d++) {
        int c = 8 * d + 2 * t;
        *(float2*)(Os + (qr + g    ) * 68 + c) = make_float2(o[d][0] * inv0, o[d][1] * inv0);
        *(float2*)(Os + (qr + g + 8) * 68 + c) = make_float2(o[d][2] * inv1, o[d][3] * inv1);
    }
    __syncthreads();
#pragma unroll
    for (int u = tid; u < 4096; u += 128) {
        int r = u >> 6, c = u & 63;
        u16 hh, ll;
        split1(Os[r * 68 + c], hh, ll);
        size_t i = (size_t)(b * SEQ + qt * 64 + r) * EMB + h * 64 + c;
        g_Oh[i] = hh; g_Ol[i] = ll;
    }
}

// ---------------------------------------------------------------------------
extern "C" void kernel_launch(void* const* d_in, const int* in_sizes, int n_in,
                              void* d_out, int out_size)
{
    const float* x  = (const float*)d_in[0];
    const float* Wq = (const float*)d_in[1];
    const float* Wk = (const float*)d_in[2];
    const float* Wv = (const float*)d_in[3];
    const float* Wo = (const float*)d_in[4];
    const float* bo = (const float*)d_in[5];
    float* out = (float*)d_out;

    cudaFuncSetAttribute(qkv_kernel,
                         cudaFuncAttributeMaxDynamicSharedMemorySize, GEMM_SMEM_BYTES);
    cudaFuncSetAttribute(proj_kernel,
                         cudaFuncAttributeMaxDynamicSharedMemorySize, GEMM_SMEM_BYTES);

    u16 *xh, *xl;
    cudaGetSymbolAddress((void**)&xh, g_xh);
    cudaGetSymbolAddress((void**)&xl, g_xl);

    // 1) split-convert inputs
    convert_kernel<<<(MROWS * EMB) / 1024, 256>>>(x, xh, xl, MROWS * EMB);
    convert_w_kernel<<<dim3((EMB * EMB) / 1024, 4), 256>>>(Wq, Wk, Wv, Wo);

    // 2) QKV projections
    qkv_kernel<<<dim3(18, 64), 256, GEMM_SMEM_BYTES>>>();

    // 3) V transpose
    vtrans_kernel<<<dim3(SEQ / 64, BH), 256>>>();

    // 4) flash attention (64-query tiles, 4 warps, R7 loads + ldmatrix)
    attn_kernel<<<dim3(SEQ / 64, HEADS, BATCH), 128>>>();

    // 5) output projection + bias
    proj_kernel<<<dim3(6, 64), 256, GEMM_SMEM_BYTES>>>(out, bo);
}

// round 15
// speedup vs baseline: 1.1915x; 1.1915x over previous
#include <cuda_runtime.h>
#include <cuda_bf16.h>
#include <cuda_fp16.h>
#include <math.h>
#include <stdint.h>

#define EMB    768
#define HEADS  12
#define DEPTH  64
#define BATCH  2
#define SEQ    4096
#define MROWS  (BATCH * SEQ)      // 8192
#define BH     (BATCH * HEADS)    // 24

typedef unsigned int  u32;
typedef unsigned short u16;

// ---------------------------------------------------------------------------
// Scratch (allocation-free device globals). Q/K/x/W in bf16 hi/lo split;
// V^T in fp16 hi/lo split (for the 2-MMA PV path).
// ---------------------------------------------------------------------------
__device__ u16 g_xh[MROWS * EMB],  g_xl[MROWS * EMB];
__device__ u16 g_Wqh[EMB * EMB],   g_Wql[EMB * EMB];
__device__ u16 g_Wkh[EMB * EMB],   g_Wkl[EMB * EMB];
__device__ u16 g_Wvh[EMB * EMB],   g_Wvl[EMB * EMB];
__device__ u16 g_Woh[EMB * EMB],   g_Wol[EMB * EMB];
__device__ u16 g_Qh[MROWS * EMB],  g_Ql[MROWS * EMB];   // Q pre-scaled by 0.125
__device__ u16 g_Kh[MROWS * EMB],  g_Kl[MROWS * EMB];
__device__ u16 g_Vh[MROWS * EMB],  g_Vl[MROWS * EMB];   // bf16 split (GEMM out)
__device__ u16 g_Vth[BH * DEPTH * SEQ], g_Vtl[BH * DEPTH * SEQ]; // fp16 V^T [bh][d][s]
__device__ u16 g_Oh[MROWS * EMB],  g_Ol[MROWS * EMB];

// ---------------------------------------------------------------------------
// Helpers
// ---------------------------------------------------------------------------
__device__ __forceinline__ void split1(float v, u16& h, u16& l) {
    __nv_bfloat16 hb = __float2bfloat16(v);
    __nv_bfloat16 lb = __float2bfloat16(v - __bfloat162float(hb));
    h = __bfloat16_as_ushort(hb);
    l = __bfloat16_as_ushort(lb);
}
// fp16 hi/lo split
__device__ __forceinline__ void split1h(float v, u16& h, u16& l) {
    __half hb = __float2half_rn(v);
    __half lb = __float2half_rn(v - __half2float(hb));
    h = __half_as_ushort(hb);
    l = __half_as_ushort(lb);
}
// pack two fp32 into f16x2 (lo = v0, hi = v1)
__device__ __forceinline__ u32 pack_f16x2(float v0, float v1) {
    u32 r;
    asm("cvt.rn.f16x2.f32 %0, %1, %2;" : "=r"(r) : "f"(v1), "f"(v0));
    return r;
}

// m16n8k16 row.col bf16 mma, fp32 accumulate (base-ISA, sm_80+)
__device__ __forceinline__ void mma16816(float* c, const u32* a, const u32* b) {
    asm volatile(
        "mma.sync.aligned.m16n8k16.row.col.f32.bf16.bf16.f32 "
        "{%0,%1,%2,%3}, {%4,%5,%6,%7}, {%8,%9}, {%0,%1,%2,%3};"
        : "+f"(c[0]), "+f"(c[1]), "+f"(c[2]), "+f"(c[3])
        : "r"(a[0]), "r"(a[1]), "r"(a[2]), "r"(a[3]), "r"(b[0]), "r"(b[1]));
}
// fp16 variant
__device__ __forceinline__ void mma16816h(float* c, const u32* a, const u32* b) {
    asm volatile(
        "mma.sync.aligned.m16n8k16.row.col.f32.f16.f16.f32 "
        "{%0,%1,%2,%3}, {%4,%5,%6,%7}, {%8,%9}, {%0,%1,%2,%3};"
        : "+f"(c[0]), "+f"(c[1]), "+f"(c[2]), "+f"(c[3])
        : "r"(a[0]), "r"(a[1]), "r"(a[2]), "r"(a[3]), "r"(b[0]), "r"(b[1]));
}

// ---------------------------------------------------------------------------
// 1) fp32 -> bf16 hi/lo elementwise converts
// ---------------------------------------------------------------------------
__global__ __launch_bounds__(256) void convert_kernel(const float* __restrict__ src,
                                                      u16* __restrict__ dh,
                                                      u16* __restrict__ dl, int n)
{
    int i = (blockIdx.x * 256 + threadIdx.x) * 4;
    if (i >= n) return;
    float4 v = *(const float4*)(src + i);
    u16 h0,l0,h1,l1,h2,l2,h3,l3;
    split1(v.x,h0,l0); split1(v.y,h1,l1); split1(v.z,h2,l2); split1(v.w,h3,l3);
    *(uint2*)(dh + i) = make_uint2((u32)h0 | ((u32)h1<<16), (u32)h2 | ((u32)h3<<16));
    *(uint2*)(dl + i) = make_uint2((u32)l0 | ((u32)l1<<16), (u32)l2 | ((u32)l3<<16));
}

__global__ __launch_bounds__(256) void convert_w_kernel(const float* __restrict__ Wq,
                                                        const float* __restrict__ Wk,
                                                        const float* __restrict__ Wv,
                                                        const float* __restrict__ Wo)
{
    const float* src; u16 *dh, *dl;
    switch (blockIdx.y) {
        case 0:  src = Wq; dh = g_Wqh; dl = g_Wql; break;
        case 1:  src = Wk; dh = g_Wkh; dl = g_Wkl; break;
        case 2:  src = Wv; dh = g_Wvh; dl = g_Wvl; break;
        default: src = Wo; dh = g_Woh; dl = g_Wol; break;
    }
    int i = (blockIdx.x * 256 + threadIdx.x) * 4;
    if (i >= EMB * EMB) return;
    float4 v = *(const float4*)(src + i);
    u16 h0,l0,h1,l1,h2,l2,h3,l3;
    split1(v.x,h0,l0); split1(v.y,h1,l1); split1(v.z,h2,l2); split1(v.w,h3,l3);
    *(uint2*)(dh + i) = make_uint2((u32)h0 | ((u32)h1<<16), (u32)h2 | ((u32)h3<<16));
    *(uint2*)(dl + i) = make_uint2((u32)l0 | ((u32)l1<<16), (u32)l2 | ((u32)l3<<16));
}

// ---------------------------------------------------------------------------
// 2) 128x128 GEMM tile via mma.sync, split-3 bf16 (unchanged; passing)
// ---------------------------------------------------------------------------
#define GS_PAD 72
#define G_TILE (128 * GS_PAD)
#define GEMM_SMEM_BYTES (4 * G_TILE * 2)   // 73728 B

__device__ __forceinline__ void gemm128(const u16* __restrict__ Ah, const u16* __restrict__ Al,
                                        const u16* __restrict__ Wh, const u16* __restrict__ Wl,
                                        int row0, int col0,
                                        int mode, float alpha,
                                        u16* __restrict__ outH, u16* __restrict__ outL,
                                        float* __restrict__ outF, const float* __restrict__ bias)
{
    extern __shared__ char smraw[];
    u16* sAh = (u16*)smraw;
    u16* sAl = sAh + G_TILE;
    u16* sWh = sAl + G_TILE;
    u16* sWl = sWh + G_TILE;

    const int tid  = threadIdx.x;
    const int warp = tid >> 5, lane = tid & 31;
    const int g = lane >> 2, t = lane & 3;
    const int r0  = (warp >> 1) * 32;
    const int c0w = (warp & 1) * 64;

    float acc[2][8][4];
#pragma unroll
    for (int i = 0; i < 2; i++)
#pragma unroll
        for (int n = 0; n < 8; n++)
#pragma unroll
            for (int q = 0; q < 4; q++) acc[i][n][q] = 0.f;

    for (int kc = 0; kc < EMB; kc += 64) {
#pragma unroll
        for (int u = tid; u < 1024; u += 256) {
            int row = u >> 3, q = u & 7;
            size_t ia = (size_t)(row0 + row) * EMB + kc + q * 8;
            size_t iw = (size_t)(col0 + row) * EMB + kc + q * 8;
            *(uint4*)(sAh + row * GS_PAD + q * 8) = *(const uint4*)(Ah + ia);
            *(uint4*)(sAl + row * GS_PAD + q * 8) = *(const uint4*)(Al + ia);
            *(uint4*)(sWh + row * GS_PAD + q * 8) = *(const uint4*)(Wh + iw);
            *(uint4*)(sWl + row * GS_PAD + q * 8) = *(const uint4*)(Wl + iw);
        }
        __syncthreads();

#pragma unroll
        for (int kb = 0; kb < 4; kb++) {
            const int kk = kb * 16 + 2 * t;
            u32 ah[2][4], al[2][4];
#pragma unroll
            for (int i = 0; i < 2; i++) {
                int rb = r0 + 16 * i;
                ah[i][0] = *(const u32*)(sAh + (rb + g    ) * GS_PAD + kk);
                ah[i][1] = *(const u32*)(sAh + (rb + g + 8) * GS_PAD + kk);
                ah[i][2] = *(const u32*)(sAh + (rb + g    ) * GS_PAD + kk + 8);
                ah[i][3] = *(const u32*)(sAh + (rb + g + 8) * GS_PAD + kk + 8);
                al[i][0] = *(const u32*)(sAl + (rb + g    ) * GS_PAD + kk);
                al[i][1] = *(const u32*)(sAl + (rb + g + 8) * GS_PAD + kk);
                al[i][2] = *(const u32*)(sAl + (rb + g    ) * GS_PAD + kk + 8);
                al[i][3] = *(const u32*)(sAl + (rb + g + 8) * GS_PAD + kk + 8);
            }
#pragma unroll
            for (int n = 0; n < 8; n++) {
                int wr = (c0w + 8 * n + g) * GS_PAD;
                u32 bh[2] = { *(const u32*)(sWh + wr + kk), *(const u32*)(sWh + wr + kk + 8) };
                u32 bl[2] = { *(const u32*)(sWl + wr + kk), *(const u32*)(sWl + wr + kk + 8) };
#pragma unroll
                for (int i = 0; i < 2; i++) {
                    mma16816(acc[i][n], ah[i], bh);
                    mma16816(acc[i][n], ah[i], bl);
                    mma16816(acc[i][n], al[i], bh);
                }
            }
        }
        __syncthreads();
    }

    float* Cs = (float*)smraw;             // [128][132]
#pragma unroll
    for (int i = 0; i < 2; i++)
#pragma unroll
        for (int n = 0; n < 8; n++) {
            int r = r0 + 16 * i + g, c = c0w + 8 * n + 2 * t;
            *(float2*)(Cs + (r    ) * 132 + c) = make_float2(acc[i][n][0], acc[i][n][1]);
            *(float2*)(Cs + (r + 8) * 132 + c) = make_float2(acc[i][n][2], acc[i][n][3]);
        }
    __syncthreads();

#pragma unroll
    for (int u = tid; u < 128 * 32; u += 256) {
        int r = u >> 5, c4 = (u & 31) * 4;
        float4 v = *(const float4*)(Cs + r * 132 + c4);
        size_t o = (size_t)(row0 + r) * EMB + col0 + c4;
        if (mode == 0) {
            v.x *= alpha; v.y *= alpha; v.z *= alpha; v.w *= alpha;
            u16 h0,l0,h1,l1,h2,l2,h3,l3;
            split1(v.x,h0,l0); split1(v.y,h1,l1); split1(v.z,h2,l2); split1(v.w,h3,l3);
            *(uint2*)(outH + o) = make_uint2((u32)h0|((u32)h1<<16), (u32)h2|((u32)h3<<16));
            *(uint2*)(outL + o) = make_uint2((u32)l0|((u32)l1<<16), (u32)l2|((u32)l3<<16));
        } else {
            float4 bv = *(const float4*)(bias + col0 + c4);
            v.x += bv.x; v.y += bv.y; v.z += bv.z; v.w += bv.w;
            *(float4*)(outF + o) = v;
        }
    }
}

__global__ __launch_bounds__(256) void qkv_kernel()
{
    int nt = blockIdx.x, sel = nt / 6;
    int col0 = (nt % 6) * 128, row0 = blockIdx.y * 128;
    const u16 *Wh, *Wl; u16 *oh, *ol; float alpha;
    if (sel == 0)      { Wh = g_Wqh; Wl = g_Wql; oh = g_Qh; ol = g_Ql; alpha = 0.125f; }
    else if (sel == 1) { Wh = g_Wkh; Wl = g_Wkl; oh = g_Kh; ol = g_Kl; alpha = 1.f; }
    else               { Wh = g_Wvh; Wl = g_Wvl; oh = g_Vh; ol = g_Vl; alpha = 1.f; }
    gemm128(g_xh, g_xl, Wh, Wl, row0, col0, 0, alpha, oh, ol, nullptr, nullptr);
}

__global__ __launch_bounds__(256) void proj_kernel(float* __restrict__ out,
                                                   const float* __restrict__ bias)
{
    gemm128(g_Oh, g_Ol, g_Woh, g_Wol, blockIdx.y * 128, blockIdx.x * 128,
            1, 1.f, nullptr, nullptr, out, bias);
}

// ---------------------------------------------------------------------------
// 3) V transpose: bf16-split V [b][s][h*64+d] -> fp16-split V^T [bh][d][s]
// ---------------------------------------------------------------------------
__global__ __launch_bounds__(256) void vtrans_kernel()
{
    __shared__ u16 Vh_s[64][GS_PAD], Vl_s[64][GS_PAD];
    int bh = blockIdx.y, b = bh / HEADS, h = bh % HEADS;
    int k0 = blockIdx.x * 64;
    int tid = threadIdx.x;
#pragma unroll
    for (int u = tid; u < 512; u += 256) {
        int row = u >> 3, q = u & 7;
        size_t i = (size_t)(b * SEQ + k0 + row) * EMB + h * 64 + q * 8;
        *(uint4*)(&Vh_s[row][q * 8]) = *(const uint4*)(g_Vh + i);
        *(uint4*)(&Vl_s[row][q * 8]) = *(const uint4*)(g_Vl + i);
    }
    __syncthreads();
#pragma unroll
    for (int u = tid; u < 4096; u += 256) {
        int d = u >> 6, key = u & 63;
        float v = __bfloat162float(__ushort_as_bfloat16(Vh_s[key][d]))
                + __bfloat162float(__ushort_as_bfloat16(Vl_s[key][d]));
        u16 hh, ll;
        split1h(v, hh, ll);                // fp16 hi/lo
        size_t o = ((size_t)bh * DEPTH + d) * SEQ + k0 + key;
        g_Vth[o] = hh;
        g_Vtl[o] = ll;
    }
}

// ---------------------------------------------------------------------------
// 4) Flash attention = R7 structure verbatim (64q tiles, 4 warps, scalar-LDS
//    just-in-time fragments). Only change: PV uses fp16 P (single) x fp16
//    V hi/lo -> 2 MMAs instead of 3, and P packing is cvt.f16x2 not split2.
// ---------------------------------------------------------------------------
#define AP 72
__global__ __launch_bounds__(128) void attn_kernel()
{
    __shared__ __align__(16) u16 smem[4 * 64 * AP];   // 36864 B
    u16* sKh = smem;
    u16* sKl = smem + 64 * AP;
    u16* sVh = smem + 2 * 64 * AP;       // fp16 V^T hi
    u16* sVl = smem + 3 * 64 * AP;       // fp16 V^T lo

    const int b = blockIdx.z, h = blockIdx.y, qt = blockIdx.x;
    const int tid = threadIdx.x, warp = tid >> 5, lane = tid & 31;
    const int g = lane >> 2, t = lane & 3;
    const int qr = warp * 16;

    // ---- load Q tile (temp in sK area), extract register fragments ----
#pragma unroll
    for (int u = tid; u < 512; u += 128) {
        int row = u >> 3, q = u & 7;
        size_t i = (size_t)(b * SEQ + qt * 64 + row) * EMB + h * 64 + q * 8;
        *(uint4*)(sKh + row * AP + q * 8) = *(const uint4*)(g_Qh + i);
        *(uint4*)(sKl + row * AP + q * 8) = *(const uint4*)(g_Ql + i);
    }
    __syncthreads();
    u32 qh[4][4], ql[4][4];
#pragma unroll
    for (int k = 0; k < 4; k++) {
        int kk = k * 16 + 2 * t;
        qh[k][0] = *(const u32*)(sKh + (qr + g    ) * AP + kk);
        qh[k][1] = *(const u32*)(sKh + (qr + g + 8) * AP + kk);
        qh[k][2] = *(const u32*)(sKh + (qr + g    ) * AP + kk + 8);
        qh[k][3] = *(const u32*)(sKh + (qr + g + 8) * AP + kk + 8);
        ql[k][0] = *(const u32*)(sKl + (qr + g    ) * AP + kk);
        ql[k][1] = *(const u32*)(sKl + (qr + g + 8) * AP + kk);
        ql[k][2] = *(const u32*)(sKl + (qr + g    ) * AP + kk + 8);
        ql[k][3] = *(const u32*)(sKl + (qr + g + 8) * AP + kk + 8);
    }
    __syncthreads();

    float o[8][4];
#pragma unroll
    for (int d = 0; d < 8; d++)
#pragma unroll
        for (int q = 0; q < 4; q++) o[d][q] = 0.f;
    float m0 = -1e30f, m1 = -1e30f, l0 = 0.f, l1 = 0.f;

    for (int kt = 0; kt < SEQ / 64; kt++) {
        // ---- stage K (bf16 split) and V^T (fp16 split) tiles ----
#pragma unroll
        for (int u = tid; u < 512; u += 128) {
            int row = u >> 3, q = u & 7;
            size_t ik = (size_t)(b * SEQ + kt * 64 + row) * EMB + h * 64 + q * 8;
            size_t iv = ((size_t)(b * HEADS + h) * DEPTH + row) * SEQ + kt * 64 + q * 8;
            *(uint4*)(sKh + row * AP + q * 8) = *(const uint4*)(g_Kh + ik);
            *(uint4*)(sKl + row * AP + q * 8) = *(const uint4*)(g_Kl + ik);
            *(uint4*)(sVh + row * AP + q * 8) = *(const uint4*)(g_Vth + iv);
            *(uint4*)(sVl + row * AP + q * 8) = *(const uint4*)(g_Vtl + iv);
        }
        __syncthreads();

        // ---- S = (0.125 Q) K^T, split-3 bf16 (unchanged) ----
        float S[8][4];
#pragma unroll
        for (int n = 0; n < 8; n++)
#pragma unroll
            for (int q = 0; q < 4; q++) S[n][q] = 0.f;
#pragma unroll
        for (int n = 0; n < 8; n++) {
            int kr = (8 * n + g) * AP;
#pragma unroll
            for (int k = 0; k < 4; k++) {
                int kk = k * 16 + 2 * t;
                u32 bh2[2] = { *(const u32*)(sKh + kr + kk), *(const u32*)(sKh + kr + kk + 8) };
                u32 bl2[2] = { *(const u32*)(sKl + kr + kk), *(const u32*)(sKl + kr + kk + 8) };
                mma16816(S[n], qh[k], bh2);
                mma16816(S[n], qh[k], bl2);
                mma16816(S[n], ql[k], bh2);
            }
        }

        // ---- online softmax on fragments (unchanged) ----
        float mx0 = -1e30f, mx1 = -1e30f;
#pragma unroll
        for (int n = 0; n < 8; n++) {
            mx0 = fmaxf(mx0, fmaxf(S[n][0], S[n][1]));
            mx1 = fmaxf(mx1, fmaxf(S[n][2], S[n][3]));
        }
        mx0 = fmaxf(mx0, __shfl_xor_sync(0xffffffffu, mx0, 1));
        mx0 = fmaxf(mx0, __shfl_xor_sync(0xffffffffu, mx0, 2));
        mx1 = fmaxf(mx1, __shfl_xor_sync(0xffffffffu, mx1, 1));
        mx1 = fmaxf(mx1, __shfl_xor_sync(0xffffffffu, mx1, 2));
        float mn0 = fmaxf(m0, mx0), mn1 = fmaxf(m1, mx1);
        float c0 = __expf(m0 - mn0), c1 = __expf(m1 - mn1);
        float s0 = 0.f, s1 = 0.f;
#pragma unroll
        for (int n = 0; n < 8; n++) {
            S[n][0] = __expf(S[n][0] - mn0); s0 += S[n][0];
            S[n][1] = __expf(S[n][1] - mn0); s0 += S[n][1];
            S[n][2] = __expf(S[n][2] - mn1); s1 += S[n][2];
            S[n][3] = __expf(S[n][3] - mn1); s1 += S[n][3];
        }
        s0 += __shfl_xor_sync(0xffffffffu, s0, 1);
        s0 += __shfl_xor_sync(0xffffffffu, s0, 2);
        s1 += __shfl_xor_sync(0xffffffffu, s1, 1);
        s1 += __shfl_xor_sync(0xffffffffu, s1, 2);
        l0 = l0 * c0 + s0;  l1 = l1 * c1 + s1;
        m0 = mn0;           m1 = mn1;
#pragma unroll
        for (int d = 0; d < 8; d++) {
            o[d][0] *= c0; o[d][1] *= c0; o[d][2] *= c1; o[d][3] *= c1;
        }

        // ---- P (C-fragment) -> fp16 A fragments (single, no split) ----
        u32 pf[4][4];
#pragma unroll
        for (int j = 0; j < 4; j++) {
            pf[j][0] = pack_f16x2(S[2*j  ][0], S[2*j  ][1]);
            pf[j][1] = pack_f16x2(S[2*j  ][2], S[2*j  ][3]);
            pf[j][2] = pack_f16x2(S[2*j+1][0], S[2*j+1][1]);
            pf[j][3] = pack_f16x2(S[2*j+1][2], S[2*j+1][3]);
        }

        // ---- O += P V : fp16, 2 MMAs per (d,j) ----
#pragma unroll
        for (int d = 0; d < 8; d++) {
            int vr = (8 * d + g) * AP;
#pragma unroll
            for (int j = 0; j < 4; j++) {
                int kk = j * 16 + 2 * t;
                u32 vh2[2] = { *(const u32*)(sVh + vr + kk), *(const u32*)(sVh + vr + kk + 8) };
                u32 vl2[2] = { *(const u32*)(sVl + vr + kk), *(const u32*)(sVl + vr + kk + 8) };
                mma16816h(o[d], pf[j], vh2);
                mma16816h(o[d], pf[j], vl2);
            }
        }
        __syncthreads();
    }

    // ---- epilogue: normalize, stage via smem, write split O ----
    float inv0 = 1.f / l0, inv1 = 1.f / l1;
    float* Os = (float*)smem;              // [64][68] fp32 = 17408 B
#pragma unroll
    for (int d = 0; d < 8; d++) {
        int c = 8 * d + 2 * t;
        *(float2*)(Os + (qr + g    ) * 68 + c) = make_float2(o[d][0] * inv0, o[d][1] * inv0);
        *(float2*)(Os + (qr + g + 8) * 68 + c) = make_float2(o[d][2] * inv1, o[d][3] * inv1);
    }
    __syncthreads();
#pragma unroll
    for (int u = tid; u < 4096; u += 128) {
        int r = u >> 6, c = u & 63;
        u16 hh, ll;
        split1(Os[r * 68 + c], hh, ll);
        size_t i = (size_t)(b * SEQ + qt * 64 + r) * EMB + h * 64 + c;
        g_Oh[i] = hh; g_Ol[i] = ll;
    }
}

// ---------------------------------------------------------------------------
extern "C" void kernel_launch(void* const* d_in, const int* in_sizes, int n_in,
                              void* d_out, int out_size)
{
    const float* x  = (const float*)d_in[0];
    const float* Wq = (const float*)d_in[1];
    const float* Wk = (const float*)d_in[2];
    const float* Wv = (const float*)d_in[3];
    const float* Wo = (const float*)d_in[4];
    const float* bo = (const float*)d_in[5];
    float* out = (float*)d_out;

    cudaFuncSetAttribute(qkv_kernel,
                         cudaFuncAttributeMaxDynamicSharedMemorySize, GEMM_SMEM_BYTES);
    cudaFuncSetAttribute(proj_kernel,
                         cudaFuncAttributeMaxDynamicSharedMemorySize, GEMM_SMEM_BYTES);

    u16 *xh, *xl;
    cudaGetSymbolAddress((void**)&xh, g_xh);
    cudaGetSymbolAddress((void**)&xl, g_xl);

    // 1) split-convert inputs
    convert_kernel<<<(MROWS * EMB) / 1024, 256>>>(x, xh, xl, MROWS * EMB);
    convert_w_kernel<<<dim3((EMB * EMB) / 1024, 4), 256>>>(Wq, Wk, Wv, Wo);

    // 2) QKV projections
    qkv_kernel<<<dim3(18, 64), 256, GEMM_SMEM_BYTES>>>();

    // 3) V transpose (bf16-split -> fp16-split V^T)
    vtrans_kernel<<<dim3(SEQ / 64, BH), 256>>>();

    // 4) flash attention (R7 structure + fp16 PV)
    attn_kernel<<<dim3(SEQ / 64, HEADS, BATCH), 128>>>();

    // 5) output projection + bias
    proj_kernel<<<dim3(6, 64), 256, GEMM_SMEM_BYTES>>>(out, bo);
}

// round 16
// speedup vs baseline: 1.1951x; 1.0030x over previous
#include <cuda_runtime.h>
#include <cuda_bf16.h>
#include <math.h>
#include <stdint.h>

#define EMB    768
#define HEADS  12
#define DEPTH  64
#define BATCH  2
#define SEQ    4096
#define MROWS  (BATCH * SEQ)      // 8192
#define BH     (BATCH * HEADS)    // 24

typedef unsigned int  u32;
typedef unsigned short u16;

// ---------------------------------------------------------------------------
// Scratch (allocation-free device globals), all bf16 hi/lo split pairs.
// ---------------------------------------------------------------------------
__device__ u16 g_xh[MROWS * EMB],  g_xl[MROWS * EMB];
__device__ u16 g_Wqh[EMB * EMB],   g_Wql[EMB * EMB];
__device__ u16 g_Wkh[EMB * EMB],   g_Wkl[EMB * EMB];
__device__ u16 g_Wvh[EMB * EMB],   g_Wvl[EMB * EMB];
__device__ u16 g_Woh[EMB * EMB],   g_Wol[EMB * EMB];
__device__ u16 g_Qh[MROWS * EMB],  g_Ql[MROWS * EMB];   // Q pre-scaled by 0.125
__device__ u16 g_Kh[MROWS * EMB],  g_Kl[MROWS * EMB];
__device__ u16 g_Vh[MROWS * EMB],  g_Vl[MROWS * EMB];
__device__ u16 g_Vth[BH * DEPTH * SEQ], g_Vtl[BH * DEPTH * SEQ]; // V^T [bh][d][s]
__device__ u16 g_Oh[MROWS * EMB],  g_Ol[MROWS * EMB];

// ---------------------------------------------------------------------------
// Helpers
// ---------------------------------------------------------------------------
__device__ __forceinline__ void split1(float v, u16& h, u16& l) {
    __nv_bfloat16 hb = __float2bfloat16(v);
    __nv_bfloat16 lb = __float2bfloat16(v - __bfloat162float(hb));
    h = __bfloat16_as_ushort(hb);
    l = __bfloat16_as_ushort(lb);
}
__device__ __forceinline__ void split2(float v0, float v1, u32& h, u32& l) {
    u16 h0, l0, h1, l1;
    split1(v0, h0, l0); split1(v1, h1, l1);
    h = (u32)h0 | ((u32)h1 << 16);
    l = (u32)l0 | ((u32)l1 << 16);
}

// m16n8k16 row.col bf16 mma, fp32 accumulate (base-ISA, sm_80+)
__device__ __forceinline__ void mma16816(float* c, const u32* a, const u32* b) {
    asm volatile(
        "mma.sync.aligned.m16n8k16.row.col.f32.bf16.bf16.f32 "
        "{%0,%1,%2,%3}, {%4,%5,%6,%7}, {%8,%9}, {%0,%1,%2,%3};"
        : "+f"(c[0]), "+f"(c[1]), "+f"(c[2]), "+f"(c[3])
        : "r"(a[0]), "r"(a[1]), "r"(a[2]), "r"(a[3]), "r"(b[0]), "r"(b[1]));
}

__device__ __forceinline__ u32 smaddr(const void* p) {
    return (u32)__cvta_generic_to_shared(p);
}
__device__ __forceinline__ void cp16(u32 dst, const void* src) {
    asm volatile("cp.async.cg.shared.global [%0], [%1], 16;" :: "r"(dst), "l"(src));
}
#define CP_COMMIT() asm volatile("cp.async.commit_group;")

// ---------------------------------------------------------------------------
// 1) fp32 -> bf16 hi/lo elementwise converts
// ---------------------------------------------------------------------------
__global__ __launch_bounds__(256) void convert_kernel(const float* __restrict__ src,
                                                      u16* __restrict__ dh,
                                                      u16* __restrict__ dl, int n)
{
    int i = (blockIdx.x * 256 + threadIdx.x) * 4;
    if (i >= n) return;
    float4 v = *(const float4*)(src + i);
    u16 h0,l0,h1,l1,h2,l2,h3,l3;
    split1(v.x,h0,l0); split1(v.y,h1,l1); split1(v.z,h2,l2); split1(v.w,h3,l3);
    *(uint2*)(dh + i) = make_uint2((u32)h0 | ((u32)h1<<16), (u32)h2 | ((u32)h3<<16));
    *(uint2*)(dl + i) = make_uint2((u32)l0 | ((u32)l1<<16), (u32)l2 | ((u32)l3<<16));
}

__global__ __launch_bounds__(256) void convert_w_kernel(const float* __restrict__ Wq,
                                                        const float* __restrict__ Wk,
                                                        const float* __restrict__ Wv,
                                                        const float* __restrict__ Wo)
{
    const float* src; u16 *dh, *dl;
    switch (blockIdx.y) {
        case 0:  src = Wq; dh = g_Wqh; dl = g_Wql; break;
        case 1:  src = Wk; dh = g_Wkh; dl = g_Wkl; break;
        case 2:  src = Wv; dh = g_Wvh; dl = g_Wvl; break;
        default: src = Wo; dh = g_Woh; dl = g_Wol; break;
    }
    int i = (blockIdx.x * 256 + threadIdx.x) * 4;
    if (i >= EMB * EMB) return;
    float4 v = *(const float4*)(src + i);
    u16 h0,l0,h1,l1,h2,l2,h3,l3;
    split1(v.x,h0,l0); split1(v.y,h1,l1); split1(v.z,h2,l2); split1(v.w,h3,l3);
    *(uint2*)(dh + i) = make_uint2((u32)h0 | ((u32)h1<<16), (u32)h2 | ((u32)h3<<16));
    *(uint2*)(dl + i) = make_uint2((u32)l0 | ((u32)l1<<16), (u32)l2 | ((u32)l3<<16));
}

// ---------------------------------------------------------------------------
// 2) 128x128 GEMM tile via mma.sync, split-3 bf16 (unchanged; passing)
// ---------------------------------------------------------------------------
#define GS_PAD 72
#define G_TILE (128 * GS_PAD)
#define GEMM_SMEM_BYTES (4 * G_TILE * 2)   // 73728 B

__device__ __forceinline__ void gemm128(const u16* __restrict__ Ah, const u16* __restrict__ Al,
                                        const u16* __restrict__ Wh, const u16* __restrict__ Wl,
                                        int row0, int col0,
                                        int mode, float alpha,
                                        u16* __restrict__ outH, u16* __restrict__ outL,
                                        float* __restrict__ outF, const float* __restrict__ bias)
{
    extern __shared__ char smraw[];
    u16* sAh = (u16*)smraw;
    u16* sAl = sAh + G_TILE;
    u16* sWh = sAl + G_TILE;
    u16* sWl = sWh + G_TILE;

    const int tid  = threadIdx.x;
    const int warp = tid >> 5, lane = tid & 31;
    const int g = lane >> 2, t = lane & 3;
    const int r0  = (warp >> 1) * 32;
    const int c0w = (warp & 1) * 64;

    float acc[2][8][4];
#pragma unroll
    for (int i = 0; i < 2; i++)
#pragma unroll
        for (int n = 0; n < 8; n++)
#pragma unroll
            for (int q = 0; q < 4; q++) acc[i][n][q] = 0.f;

    for (int kc = 0; kc < EMB; kc += 64) {
#pragma unroll
        for (int u = tid; u < 1024; u += 256) {
            int row = u >> 3, q = u & 7;
            size_t ia = (size_t)(row0 + row) * EMB + kc + q * 8;
            size_t iw = (size_t)(col0 + row) * EMB + kc + q * 8;
            *(uint4*)(sAh + row * GS_PAD + q * 8) = *(const uint4*)(Ah + ia);
            *(uint4*)(sAl + row * GS_PAD + q * 8) = *(const uint4*)(Al + ia);
            *(uint4*)(sWh + row * GS_PAD + q * 8) = *(const uint4*)(Wh + iw);
            *(uint4*)(sWl + row * GS_PAD + q * 8) = *(const uint4*)(Wl + iw);
        }
        __syncthreads();

#pragma unroll
        for (int kb = 0; kb < 4; kb++) {
            const int kk = kb * 16 + 2 * t;
            u32 ah[2][4], al[2][4];
#pragma unroll
            for (int i = 0; i < 2; i++) {
                int rb = r0 + 16 * i;
                ah[i][0] = *(const u32*)(sAh + (rb + g    ) * GS_PAD + kk);
                ah[i][1] = *(const u32*)(sAh + (rb + g + 8) * GS_PAD + kk);
                ah[i][2] = *(const u32*)(sAh + (rb + g    ) * GS_PAD + kk + 8);
                ah[i][3] = *(const u32*)(sAh + (rb + g + 8) * GS_PAD + kk + 8);
                al[i][0] = *(const u32*)(sAl + (rb + g    ) * GS_PAD + kk);
                al[i][1] = *(const u32*)(sAl + (rb + g + 8) * GS_PAD + kk);
                al[i][2] = *(const u32*)(sAl + (rb + g    ) * GS_PAD + kk + 8);
                al[i][3] = *(const u32*)(sAl + (rb + g + 8) * GS_PAD + kk + 8);
            }
#pragma unroll
            for (int n = 0; n < 8; n++) {
                int wr = (c0w + 8 * n + g) * GS_PAD;
                u32 bh[2] = { *(const u32*)(sWh + wr + kk), *(const u32*)(sWh + wr + kk + 8) };
                u32 bl[2] = { *(const u32*)(sWl + wr + kk), *(const u32*)(sWl + wr + kk + 8) };
#pragma unroll
                for (int i = 0; i < 2; i++) {
                    mma16816(acc[i][n], ah[i], bh);
                    mma16816(acc[i][n], ah[i], bl);
                    mma16816(acc[i][n], al[i], bh);
                }
            }
        }
        __syncthreads();
    }

    float* Cs = (float*)smraw;             // [128][132]
#pragma unroll
    for (int i = 0; i < 2; i++)
#pragma unroll
        for (int n = 0; n < 8; n++) {
            int r = r0 + 16 * i + g, c = c0w + 8 * n + 2 * t;
            *(float2*)(Cs + (r    ) * 132 + c) = make_float2(acc[i][n][0], acc[i][n][1]);
            *(float2*)(Cs + (r + 8) * 132 + c) = make_float2(acc[i][n][2], acc[i][n][3]);
        }
    __syncthreads();

#pragma unroll
    for (int u = tid; u < 128 * 32; u += 256) {
        int r = u >> 5, c4 = (u & 31) * 4;
        float4 v = *(const float4*)(Cs + r * 132 + c4);
        size_t o = (size_t)(row0 + r) * EMB + col0 + c4;
        if (mode == 0) {
            v.x *= alpha; v.y *= alpha; v.z *= alpha; v.w *= alpha;
            u16 h0,l0,h1,l1,h2,l2,h3,l3;
            split1(v.x,h0,l0); split1(v.y,h1,l1); split1(v.z,h2,l2); split1(v.w,h3,l3);
            *(uint2*)(outH + o) = make_uint2((u32)h0|((u32)h1<<16), (u32)h2|((u32)h3<<16));
            *(uint2*)(outL + o) = make_uint2((u32)l0|((u32)l1<<16), (u32)l2|((u32)l3<<16));
        } else {
            float4 bv = *(const float4*)(bias + col0 + c4);
            v.x += bv.x; v.y += bv.y; v.z += bv.z; v.w += bv.w;
            *(float4*)(outF + o) = v;
        }
    }
}

__global__ __launch_bounds__(256) void qkv_kernel()
{
    int nt = blockIdx.x, sel = nt / 6;
    int col0 = (nt % 6) * 128, row0 = blockIdx.y * 128;
    const u16 *Wh, *Wl; u16 *oh, *ol; float alpha;
    if (sel == 0)      { Wh = g_Wqh; Wl = g_Wql; oh = g_Qh; ol = g_Ql; alpha = 0.125f; }
    else if (sel == 1) { Wh = g_Wkh; Wl = g_Wkl; oh = g_Kh; ol = g_Kl; alpha = 1.f; }
    else               { Wh = g_Wvh; Wl = g_Wvl; oh = g_Vh; ol = g_Vl; alpha = 1.f; }
    gemm128(g_xh, g_xl, Wh, Wl, row0, col0, 0, alpha, oh, ol, nullptr, nullptr);
}

__global__ __launch_bounds__(256) void proj_kernel(float* __restrict__ out,
                                                   const float* __restrict__ bias)
{
    gemm128(g_Oh, g_Ol, g_Woh, g_Wol, blockIdx.y * 128, blockIdx.x * 128,
            1, 1.f, nullptr, nullptr, out, bias);
}

// ---------------------------------------------------------------------------
// 3) V transpose: g_Vh/l [b][s][h*64+d] -> g_Vth/l [bh][d][s]
// ---------------------------------------------------------------------------
__global__ __launch_bounds__(256) void vtrans_kernel()
{
    __shared__ u16 Vh_s[64][GS_PAD], Vl_s[64][GS_PAD];
    int bh = blockIdx.y, b = bh / HEADS, h = bh % HEADS;
    int k0 = blockIdx.x * 64;
    int tid = threadIdx.x;
#pragma unroll
    for (int u = tid; u < 512; u += 256) {
        int row = u >> 3, q = u & 7;
        size_t i = (size_t)(b * SEQ + k0 + row) * EMB + h * 64 + q * 8;
        *(uint4*)(&Vh_s[row][q * 8]) = *(const uint4*)(g_Vh + i);
        *(uint4*)(&Vl_s[row][q * 8]) = *(const uint4*)(g_Vl + i);
    }
    __syncthreads();
#pragma unroll
    for (int u = tid; u < 4096; u += 256) {
        int d = u >> 6, key = u & 63;
        size_t o = ((size_t)bh * DEPTH + d) * SEQ + k0 + key;
        g_Vth[o] = Vh_s[key][d];
        g_Vtl[o] = Vl_s[key][d];
    }
}

// ---------------------------------------------------------------------------
// 4) Flash attention = R7 compute structure (64q tiles, 4 warps, scalar-LDS
//    just-in-time fragments, split-3 both paths). Only change vs R7:
//    K/V staging is cp.async double-buffered (hides the L2 latency that the
//    blocking LDG->STS chain exposed each tile).
// ---------------------------------------------------------------------------
#define AP 72                              // u16 per smem row (144 B)
#define ARR_U16 (64 * AP)                  // one 64-row array
#define STAGE_U16 (4 * ARR_U16)            // Kh,Kl,Vh,Vl
#define ATTN_SMEM_BYTES (2 * STAGE_U16 * 2)  // 73728 B

// stage one K/V tile (kt) into stage s via cp.async (2048 x 16B chunks)
__device__ __forceinline__ void attn_stage(int kt, int s, int b, int h,
                                           int tid, u32 smb)
{
#pragma unroll
    for (int u = tid; u < 2048; u += 128) {
        int a = u >> 9, row = (u >> 3) & 63, q = u & 7;
        const u16* src; size_t off;
        if (a < 2) {
            src = (a == 0) ? g_Kh : g_Kl;
            off = (size_t)(b * SEQ + kt * 64 + row) * EMB + h * 64 + q * 8;
        } else {
            src = (a == 2) ? g_Vth : g_Vtl;
            off = ((size_t)(b * HEADS + h) * DEPTH + row) * SEQ + kt * 64 + q * 8;
        }
        u32 dst = smb + (u32)(s * STAGE_U16 + a * ARR_U16 + row * AP + q * 8) * 2;
        cp16(dst, src + off);
    }
    CP_COMMIT();
}

__global__ __launch_bounds__(128) void attn_kernel()
{
    extern __shared__ char smraw[];
    u16* sm = (u16*)smraw;
    const u32 smb = smaddr(sm);

    const int b = blockIdx.z, h = blockIdx.y, qt = blockIdx.x;
    const int tid = threadIdx.x, warp = tid >> 5, lane = tid & 31;
    const int g = lane >> 2, t = lane & 3;
    const int qr = warp * 16;

    // ---- load Q tile into stage-0 area, extract fragments (scalar LDS) ----
    u16* sQh = sm;
    u16* sQl = sm + ARR_U16;
#pragma unroll
    for (int u = tid; u < 512; u += 128) {
        int row = u >> 3, q = u & 7;
        size_t i = (size_t)(b * SEQ + qt * 64 + row) * EMB + h * 64 + q * 8;
        *(uint4*)(sQh + row * AP + q * 8) = *(const uint4*)(g_Qh + i);
        *(uint4*)(sQl + row * AP + q * 8) = *(const uint4*)(g_Ql + i);
    }
    __syncthreads();
    u32 qh[4][4], ql[4][4];
#pragma unroll
    for (int k = 0; k < 4; k++) {
        int kk = k * 16 + 2 * t;
        qh[k][0] = *(const u32*)(sQh + (qr + g    ) * AP + kk);
        qh[k][1] = *(const u32*)(sQh + (qr + g + 8) * AP + kk);
        qh[k][2] = *(const u32*)(sQh + (qr + g    ) * AP + kk + 8);
        qh[k][3] = *(const u32*)(sQh + (qr + g + 8) * AP + kk + 8);
        ql[k][0] = *(const u32*)(sQl + (qr + g    ) * AP + kk);
        ql[k][1] = *(const u32*)(sQl + (qr + g + 8) * AP + kk);
        ql[k][2] = *(const u32*)(sQl + (qr + g    ) * AP + kk + 8);
        ql[k][3] = *(const u32*)(sQl + (qr + g + 8) * AP + kk + 8);
    }
    __syncthreads();                       // Q extracted; stage area reusable

    float o[8][4];
#pragma unroll
    for (int d = 0; d < 8; d++)
#pragma unroll
        for (int q = 0; q < 4; q++) o[d][q] = 0.f;
    float m0 = -1e30f, m1 = -1e30f, l0 = 0.f, l1 = 0.f;

    attn_stage(0, 0, b, h, tid, smb);      // preload first tile

    for (int kt = 0; kt < SEQ / 64; kt++) {
        const int cur = kt & 1;
        if (kt + 1 < SEQ / 64) {
            attn_stage(kt + 1, cur ^ 1, b, h, tid, smb);
            asm volatile("cp.async.wait_group 1;");
        } else {
            asm volatile("cp.async.wait_group 0;");
        }
        __syncthreads();                   // stage `cur` visible

        u16* sKh = sm + cur * STAGE_U16;
        u16* sKl = sKh + ARR_U16;
        u16* sVh = sKl + ARR_U16;
        u16* sVl = sVh + ARR_U16;

        // ---- S = (0.125 Q) K^T, split-3, scalar just-in-time LDS ----
        float S[8][4];
#pragma unroll
        for (int n = 0; n < 8; n++)
#pragma unroll
            for (int q = 0; q < 4; q++) S[n][q] = 0.f;
#pragma unroll
        for (int n = 0; n < 8; n++) {
            int kr = (8 * n + g) * AP;
#pragma unroll
            for (int k = 0; k < 4; k++) {
                int kk = k * 16 + 2 * t;
                u32 bh2[2] = { *(const u32*)(sKh + kr + kk), *(const u32*)(sKh + kr + kk + 8) };
                u32 bl2[2] = { *(const u32*)(sKl + kr + kk), *(const u32*)(sKl + kr + kk + 8) };
                mma16816(S[n], qh[k], bh2);
                mma16816(S[n], qh[k], bl2);
                mma16816(S[n], ql[k], bh2);
            }
        }

        // ---- online softmax on fragments ----
        float mx0 = -1e30f, mx1 = -1e30f;
#pragma unroll
        for (int n = 0; n < 8; n++) {
            mx0 = fmaxf(mx0, fmaxf(S[n][0], S[n][1]));
            mx1 = fmaxf(mx1, fmaxf(S[n][2], S[n][3]));
        }
        mx0 = fmaxf(mx0, __shfl_xor_sync(0xffffffffu, mx0, 1));
        mx0 = fmaxf(mx0, __shfl_xor_sync(0xffffffffu, mx0, 2));
        mx1 = fmaxf(mx1, __shfl_xor_sync(0xffffffffu, mx1, 1));
        mx1 = fmaxf(mx1, __shfl_xor_sync(0xffffffffu, mx1, 2));
        float mn0 = fmaxf(m0, mx0), mn1 = fmaxf(m1, mx1);
        float c0 = __expf(m0 - mn0), c1 = __expf(m1 - mn1);
        float s0 = 0.f, s1 = 0.f;
#pragma unroll
        for (int n = 0; n < 8; n++) {
            S[n][0] = __expf(S[n][0] - mn0); s0 += S[n][0];
            S[n][1] = __expf(S[n][1] - mn0); s0 += S[n][1];
            S[n][2] = __expf(S[n][2] - mn1); s1 += S[n][2];
            S[n][3] = __expf(S[n][3] - mn1); s1 += S[n][3];
        }
        s0 += __shfl_xor_sync(0xffffffffu, s0, 1);
        s0 += __shfl_xor_sync(0xffffffffu, s0, 2);
        s1 += __shfl_xor_sync(0xffffffffu, s1, 1);
        s1 += __shfl_xor_sync(0xffffffffu, s1, 2);
        l0 = l0 * c0 + s0;  l1 = l1 * c1 + s1;
        m0 = mn0;           m1 = mn1;
#pragma unroll
        for (int d = 0; d < 8; d++) {
            o[d][0] *= c0; o[d][1] *= c0; o[d][2] *= c1; o[d][3] *= c1;
        }

        // ---- P (C-fragment) -> A fragments, split hi/lo ----
        u32 ph[4][4], pl[4][4];
#pragma unroll
        for (int j = 0; j < 4; j++) {
            split2(S[2*j  ][0], S[2*j  ][1], ph[j][0], pl[j][0]);
            split2(S[2*j  ][2], S[2*j  ][3], ph[j][1], pl[j][1]);
            split2(S[2*j+1][0], S[2*j+1][1], ph[j][2], pl[j][2]);
            split2(S[2*j+1][2], S[2*j+1][3], ph[j][3], pl[j][3]);
        }

        // ---- O += P V, split-3, scalar just-in-time LDS ----
#pragma unroll
        for (int d = 0; d < 8; d++) {
            int vr = (8 * d + g) * AP;
#pragma unroll
            for (int j = 0; j < 4; j++) {
                int kk = j * 16 + 2 * t;
                u32 bh2[2] = { *(const u32*)(sVh + vr + kk), *(const u32*)(sVh + vr + kk + 8) };
                u32 bl2[2] = { *(const u32*)(sVl + vr + kk), *(const u32*)(sVl + vr + kk + 8) };
                mma16816(o[d], ph[j], bh2);
                mma16816(o[d], ph[j], bl2);
                mma16816(o[d], pl[j], bh2);
            }
        }
        __syncthreads();                   // done reading stage `cur`
    }

    // ---- epilogue: normalize, stage via smem, write split O ----
    float inv0 = 1.f / l0, inv1 = 1.f / l1;
    float* Os = (float*)smraw;             // [64][68] fp32 = 17408 B
#pragma unroll
    for (int d = 0; d < 8; d++) {
        int c = 8 * d + 2 * t;
        *(float2*)(Os + (qr + g    ) * 68 + c) = make_float2(o[d][0] * inv0, o[d][1] * inv0);
        *(float2*)(Os + (qr + g + 8) * 68 + c) = make_float2(o[d][2] * inv1, o[d][3] * inv1);
    }
    __syncthreads();
#pragma unroll
    for (int u = tid; u < 4096; u += 128) {
        int r = u >> 6, c = u & 63;
        u16 hh, ll;
        split1(Os[r * 68 + c], hh, ll);
        size_t i = (size_t)(b * SEQ + qt * 64 + r) * EMB + h * 64 + c;
        g_Oh[i] = hh; g_Ol[i] = ll;
    }
}

// ---------------------------------------------------------------------------
extern "C" void kernel_launch(void* const* d_in, const int* in_sizes, int n_in,
                              void* d_out, int out_size)
{
    const float* x  = (const float*)d_in[0];
    const float* Wq = (const float*)d_in[1];
    const float* Wk = (const float*)d_in[2];
    const float* Wv = (const float*)d_in[3];
    const float* Wo = (const float*)d_in[4];
    const float* bo = (const float*)d_in[5];
    float* out = (float*)d_out;

    cudaFuncSetAttribute(qkv_kernel,
                         cudaFuncAttributeMaxDynamicSharedMemorySize, GEMM_SMEM_BYTES);
    cudaFuncSetAttribute(proj_kernel,
                         cudaFuncAttributeMaxDynamicSharedMemorySize, GEMM_SMEM_BYTES);
    cudaFuncSetAttribute(attn_kernel,
                         cudaFuncAttributeMaxDynamicSharedMemorySize, ATTN_SMEM_BYTES);

    u16 *xh, *xl;
    cudaGetSymbolAddress((void**)&xh, g_xh);
    cudaGetSymbolAddress((void**)&xl, g_xl);

    // 1) split-convert inputs
    convert_kernel<<<(MROWS * EMB) / 1024, 256>>>(x, xh, xl, MROWS * EMB);
    convert_w_kernel<<<dim3((EMB * EMB) / 1024, 4), 256>>>(Wq, Wk, Wv, Wo);

    // 2) QKV projections
    qkv_kernel<<<dim3(18, 64), 256, GEMM_SMEM_BYTES>>>();

    // 3) V transpose
    vtrans_kernel<<<dim3(SEQ / 64, BH), 256>>>();

    // 4) flash attention (R7 compute + cp.async double-buffered staging)
    attn_kernel<<<dim3(SEQ / 64, HEADS, BATCH), 128, ATTN_SMEM_BYTES>>>();

    // 5) output projection + bias
    proj_kernel<<<dim3(6, 64), 256, GEMM_SMEM_BYTES>>>(out, bo);
}